// round 17
// baseline (speedup 1.0000x reference)
#include <cuda_runtime.h>
#include <cuda_fp16.h>
#include <math.h>
#include <cstdint>

// Problem constants
#define T_SEQ   2048
#define C_EMB   2048
#define N_HEADS 16
#define N_KVH   4
#define HEAD_D  128
#define KV_W    (N_KVH * HEAD_D)   // 512
#define QKV_W   (C_EMB + 2 * KV_W) // 3072

// -------- scratch (device globals; no allocation allowed) --------
__device__ __half g_qh[T_SEQ * C_EMB];          // roped Q * log2e/sqrt(d), half
__device__ __half g_kh[N_KVH * T_SEQ * HEAD_D];
__device__ __half g_vh[N_KVH * T_SEQ * HEAD_D];
__device__ __half g_yh[T_SEQ * C_EMB];
__device__ __half g_xh[T_SEQ * C_EMB];
__device__ __half g_wqkvt[QKV_W * C_EMB];
__device__ __half g_wot[C_EMB * C_EMB];
__device__ float  g_bqkv[QKV_W];

// =====================================================================
// helpers
// =====================================================================
__device__ __forceinline__ uint32_t smem_u32(const void* p) {
    uint32_t a;
    asm("{ .reg .u64 t; cvta.to.shared.u64 t, %1; cvt.u32.u64 %0, t; }" : "=r"(a) : "l"(p));
    return a;
}
__device__ __forceinline__ void cp_async16(uint32_t dst, const void* src) {
    asm volatile("cp.async.ca.shared.global [%0], [%1], 16;" :: "r"(dst), "l"(src) : "memory");
}
__device__ __forceinline__ void cp_commit() {
    asm volatile("cp.async.commit_group;" ::: "memory");
}
template <int N>
__device__ __forceinline__ void cp_wait() {
    asm volatile("cp.async.wait_group %0;" :: "n"(N) : "memory");
}
__device__ __forceinline__ void ldm_x4(unsigned* r, uint32_t addr) {
    asm volatile("ldmatrix.sync.aligned.m8n8.x4.shared.b16 {%0,%1,%2,%3}, [%4];"
        : "=r"(r[0]), "=r"(r[1]), "=r"(r[2]), "=r"(r[3]) : "r"(addr));
}
__device__ __forceinline__ void ldm_x4t(unsigned* r, uint32_t addr) {
    asm volatile("ldmatrix.sync.aligned.m8n8.x4.trans.shared.b16 {%0,%1,%2,%3}, [%4];"
        : "=r"(r[0]), "=r"(r[1]), "=r"(r[2]), "=r"(r[3]) : "r"(addr));
}
__device__ __forceinline__ void mma_f16(float* c, const unsigned* a, const unsigned* b) {
    asm volatile(
        "mma.sync.aligned.m16n8k16.row.col.f32.f16.f16.f32 "
        "{%0,%1,%2,%3}, {%4,%5,%6,%7}, {%8,%9}, {%0,%1,%2,%3};"
        : "+f"(c[0]), "+f"(c[1]), "+f"(c[2]), "+f"(c[3])
        : "r"(a[0]), "r"(a[1]), "r"(a[2]), "r"(a[3]), "r"(b[0]), "r"(b[1]));
}
__device__ __forceinline__ unsigned pack_h2(float a, float b) {
    __half2 h = __floats2half2_rn(a, b);
    return *reinterpret_cast<unsigned*>(&h);
}
__device__ __forceinline__ float ex2(float x) {
    float y;
    asm("ex2.approx.f32 %0, %1;" : "=f"(y) : "f"(x));
    return y;
}
__device__ __forceinline__ int sec3(int d) {
    if (d < 16)  return 0;
    if (d < 40)  return 1;
    if (d < 64)  return 2;
    if (d < 80)  return 0;
    if (d < 104) return 1;
    return 2;
}

// =====================================================================
// GEMM config (validated R14): CTA 128x128, 4 warps of 64x64,
// 128 threads, 4 slots BK=32, 2 k-tiles per sync, 2 CTAs/SM.
// =====================================================================
#define GROWB     80
#define G_ASZ     (128 * GROWB)               // 10240
#define SLOT_SZ   (2 * G_ASZ)                 // 20480
#define GSMEM     (4 * SLOT_SZ)               // 81920

#define GEMM_MAINLOOP(A_, B_, K_)                                              \
    float acc[4][8][4];                                                        \
    _Pragma("unroll")                                                          \
    for (int mt = 0; mt < 4; mt++)                                             \
        _Pragma("unroll")                                                      \
        for (int nt = 0; nt < 8; nt++)                                         \
            _Pragma("unroll")                                                  \
            for (int r = 0; r < 4; r++) acc[mt][nt][r] = 0.f;                  \
    const int NS = (K_) / 64;                                                  \
    LOAD_TILE(A_, B_, K_, 0);                                                  \
    LOAD_TILE(A_, B_, K_, 1);                                                  \
    cp_commit();                                                               \
    for (int s = 0; s < NS; s++) {                                             \
        __syncthreads();                                                       \
        if (s + 1 < NS) {                                                      \
            LOAD_TILE(A_, B_, K_, 2 * s + 2);                                  \
            LOAD_TILE(A_, B_, K_, 2 * s + 3);                                  \
            cp_commit();                                                       \
            cp_wait<1>();                                                      \
        } else {                                                               \
            cp_wait<0>();                                                      \
        }                                                                      \
        __syncthreads();                                                       \
        _Pragma("unroll")                                                      \
        for (int q = 0; q < 2; q++) {                                          \
            const uint32_t soff = (uint32_t)(((2 * s + q) & 3) * SLOT_SZ);     \
            _Pragma("unroll")                                                  \
            for (int ks = 0; ks < 2; ks++) {                                   \
                unsigned af[4][4], bf[4][4];                                   \
                _Pragma("unroll")                                              \
                for (int mt = 0; mt < 4; mt++)                                 \
                    ldm_x4(af[mt], a_base + soff + (uint32_t)(mt * 16 * GROWB + ks * 32)); \
                _Pragma("unroll")                                              \
                for (int pr = 0; pr < 4; pr++)                                 \
                    ldm_x4(bf[pr], b_base + soff + (uint32_t)(pr * 16 * GROWB + ks * 32)); \
                _Pragma("unroll")                                              \
                for (int mt = 0; mt < 4; mt++)                                 \
                    _Pragma("unroll")                                          \
                    for (int nt = 0; nt < 8; nt++)                             \
                        mma_f16(acc[mt][nt], af[mt], &bf[nt >> 1][(nt & 1) * 2]); \
            }                                                                  \
        }                                                                      \
    }

#define LOAD_TILE(A_, B_, K_, kt)                                              \
    do {                                                                       \
        const uint32_t so = (uint32_t)(((kt) & 3) * SLOT_SZ);                  \
        const __half* Ak = (A_) + (size_t)m0 * (K_) + (size_t)(kt) * 32;       \
        const __half* Bk = (B_) + (size_t)n0 * (K_) + (size_t)(kt) * 32;       \
        _Pragma("unroll")                                                      \
        for (int it = 0; it < 4; it++) {                                       \
            int idx = tid + it * 128;                                          \
            int row = idx >> 2, c = idx & 3;                                   \
            cp_async16(sbase + so + (uint32_t)(row * GROWB + c * 16),          \
                       Ak + (size_t)row * (K_) + c * 8);                       \
            cp_async16(sbase + so + G_ASZ + (uint32_t)(row * GROWB + c * 16),  \
                       Bk + (size_t)row * (K_) + c * 8);                       \
        }                                                                      \
    } while (0)

// =====================================================================
// plain GEMM (for O-projection): C fp32 output (+ optional bias)
// =====================================================================
__global__ __launch_bounds__(128, 2)
void gemm_h(const __half* __restrict__ A, const __half* __restrict__ Bt,
            const float* __restrict__ bias, float* __restrict__ C,
            int M, int N, int K)
{
    extern __shared__ char smem[];
    const uint32_t sbase = smem_u32(smem);

    const int tid  = threadIdx.x;
    const int warp = tid >> 5;
    const int lane = tid & 31;
    const int g    = lane >> 2;
    const int tg   = lane & 3;
    const int wm   = warp >> 1;
    const int wn   = warp & 1;
    const int m0   = blockIdx.y * 128;
    const int n0   = blockIdx.x * 128;

    const int lr8  = lane & 7;
    const int rsel = (lane >> 3) & 1;
    const int ksel = (lane >> 4) & 1;
    const uint32_t a_base = sbase +
        (uint32_t)((wm * 64 + lr8 + rsel * 8) * GROWB + ksel * 16);
    const uint32_t b_base = sbase + G_ASZ +
        (uint32_t)((wn * 64 + lr8 + ksel * 8) * GROWB + rsel * 16);

    GEMM_MAINLOOP(A, Bt, K)

#pragma unroll
    for (int mt = 0; mt < 4; mt++) {
        int r0 = m0 + wm * 64 + mt * 16 + g;
#pragma unroll
        for (int nt = 0; nt < 8; nt++) {
            int c = n0 + wn * 64 + nt * 8 + 2 * tg;
            float bx = 0.f, by = 0.f;
            if (bias) { bx = bias[c]; by = bias[c + 1]; }
            float2 v0 = make_float2(acc[mt][nt][0] + bx, acc[mt][nt][1] + by);
            float2 v1 = make_float2(acc[mt][nt][2] + bx, acc[mt][nt][3] + by);
            *(float2*)&C[(size_t)r0 * N + c]       = v0;
            *(float2*)&C[(size_t)(r0 + 8) * N + c] = v1;
        }
    }
}

// =====================================================================
// QKV GEMM with fused RoPE epilogue. Grid (24, 16); each CTA's 128-col
// block is exactly one head. Q: rope+prescale(log2e/sqrt(d))->g_qh.
// K: rope->g_kh + out_k. V: ->g_vh + out_v.
// =====================================================================
__global__ __launch_bounds__(128, 2)
void gemm_qkv(const __half* __restrict__ A, const __half* __restrict__ Bt,
              const float* __restrict__ bias,
              const float* __restrict__ cosb, const float* __restrict__ sinb,
              float* __restrict__ out_k, float* __restrict__ out_v, int K)
{
    extern __shared__ char smem[];
    const uint32_t sbase = smem_u32(smem);

    const int tid  = threadIdx.x;
    const int warp = tid >> 5;
    const int lane = tid & 31;
    const int g    = lane >> 2;
    const int tg   = lane & 3;
    const int wm   = warp >> 1;
    const int wn   = warp & 1;
    const int m0   = blockIdx.y * 128;
    const int n0   = blockIdx.x * 128;

    const int lr8  = lane & 7;
    const int rsel = (lane >> 3) & 1;
    const int ksel = (lane >> 4) & 1;
    const uint32_t a_base = sbase +
        (uint32_t)((wm * 64 + lr8 + rsel * 8) * GROWB + ksel * 16);
    const uint32_t b_base = sbase + G_ASZ +
        (uint32_t)((wn * 64 + lr8 + ksel * 8) * GROWB + rsel * 16);

    GEMM_MAINLOOP(A, Bt, K)

    // ---- fused epilogue ----
    __syncthreads();   // done reading pipeline slots; smem reused below
    float* st = (float*)smem;   // [128][132]

#pragma unroll
    for (int mt = 0; mt < 4; mt++) {
        int r = wm * 64 + mt * 16 + g;
#pragma unroll
        for (int nt = 0; nt < 8; nt++) {
            int c = wn * 64 + nt * 8 + 2 * tg;
            float bx = bias[n0 + c], by = bias[n0 + c + 1];
            st[r * 132 + c]           = acc[mt][nt][0] + bx;
            st[r * 132 + c + 1]       = acc[mt][nt][1] + by;
            st[(r + 8) * 132 + c]     = acc[mt][nt][2] + bx;
            st[(r + 8) * 132 + c + 1] = acc[mt][nt][3] + by;
        }
    }
    __syncthreads();

    const int hb = n0 >> 7;   // 0..23
    if (hb >= 20) {
        // V head: coalesced dual store
        const int kvh = hb - 20;
        float*  ov = out_v + (size_t)kvh * T_SEQ * HEAD_D + (size_t)m0 * HEAD_D;
        __half* vh = g_vh  + (size_t)kvh * T_SEQ * HEAD_D + (size_t)m0 * HEAD_D;
        for (int rr = 0; rr < 128; rr++) {
            float v = st[rr * 132 + tid];
            ov[rr * HEAD_D + tid] = v;
            vh[rr * HEAD_D + tid] = __float2half(v);
        }
        return;
    }

    // Q or K: rope. thread owns pair (d, d+64), two-row parallel.
    const int d    = tid & 63;
    const int rpar = tid >> 6;     // 0 or 1
    const int d2   = d + 64;
    const float* cp1 = cosb + (size_t)sec3(d)  * T_SEQ * HEAD_D + (size_t)m0 * HEAD_D + d;
    const float* sp1 = sinb + (size_t)sec3(d)  * T_SEQ * HEAD_D + (size_t)m0 * HEAD_D + d;
    const float* cp2 = cosb + (size_t)sec3(d2) * T_SEQ * HEAD_D + (size_t)m0 * HEAD_D + d2;
    const float* sp2 = sinb + (size_t)sec3(d2) * T_SEQ * HEAD_D + (size_t)m0 * HEAD_D + d2;

    if (hb < 16) {
        const float qs2 = 0.08838834764831845f * 1.4426950408889634f;  // 1/sqrt(d)*log2e
        __half* qh = g_qh + (size_t)m0 * C_EMB + hb * HEAD_D;
        for (int rr = rpar; rr < 128; rr += 2) {
            float c1 = cp1[rr * HEAD_D], s1 = sp1[rr * HEAD_D];
            float c2 = cp2[rr * HEAD_D], s2 = sp2[rr * HEAD_D];
            float x1 = st[rr * 132 + d], x2 = st[rr * 132 + d2];
            qh[(size_t)rr * C_EMB + d]  = __float2half((x1 * c1 - x2 * s1) * qs2);
            qh[(size_t)rr * C_EMB + d2] = __float2half((x2 * c2 + x1 * s2) * qs2);
        }
    } else {
        const int kvh = hb - 16;
        const size_t ob = (size_t)kvh * T_SEQ * HEAD_D + (size_t)m0 * HEAD_D;
        for (int rr = rpar; rr < 128; rr += 2) {
            float c1 = cp1[rr * HEAD_D], s1 = sp1[rr * HEAD_D];
            float c2 = cp2[rr * HEAD_D], s2 = sp2[rr * HEAD_D];
            float x1 = st[rr * 132 + d], x2 = st[rr * 132 + d2];
            float r1 = x1 * c1 - x2 * s1;
            float r2 = x2 * c2 + x1 * s2;
            out_k[ob + rr * HEAD_D + d]  = r1;
            out_k[ob + rr * HEAD_D + d2] = r2;
            g_kh[ob + rr * HEAD_D + d]   = __float2half(r1);
            g_kh[ob + rr * HEAD_D + d2]  = __float2half(r2);
        }
    }
}
#undef LOAD_TILE

// =====================================================================
// fused prep: z=0..3 weight transposes, z=4 convx + bias concat
// =====================================================================
__global__ __launch_bounds__(256)
void prep_kernel(const float* __restrict__ Wq, const float* __restrict__ Wk,
                 const float* __restrict__ Wv, const float* __restrict__ Wo,
                 const float* __restrict__ bq, const float* __restrict__ bk,
                 const float* __restrict__ bv, const float* __restrict__ x)
{
    const int z = blockIdx.z;
    const int tid = threadIdx.y * 32 + threadIdx.x;

    if (z == 4) {
        const int bid = blockIdx.y * 64 + blockIdx.x;
        int i = (bid * 256 + tid) * 4;
        float4 v = *(const float4*)&x[i];
        *(__half2*)&g_xh[i]     = __floats2half2_rn(v.x, v.y);
        *(__half2*)&g_xh[i + 2] = __floats2half2_rn(v.z, v.w);
        if (bid < 12) {
            int idx = bid * 256 + tid;
            float b = (idx < 2048) ? bq[idx]
                    : (idx < 2560) ? bk[idx - 2048]
                                   : bv[idx - 2560];
            g_bqkv[idx] = b;
        }
        return;
    }

    __shared__ float tile[32][33];
    const float* in;
    __half* out;
    int C;
    if (z == 0)      { in = Wq; out = g_wqkvt;               C = C_EMB; }
    else if (z == 1) { in = Wk; out = g_wqkvt + 2048 * 2048; C = KV_W; }
    else if (z == 2) { in = Wv; out = g_wqkvt + 2560 * 2048; C = KV_W; }
    else             { in = Wo; out = g_wot;                 C = C_EMB; }
    const int bx = blockIdx.x * 32;
    if (bx >= C) return;
    const int by = blockIdx.y * 32;
    const int R = C_EMB;
    const int xx = bx + threadIdx.x;
#pragma unroll
    for (int i = threadIdx.y; i < 32; i += 8)
        tile[i][threadIdx.x] = in[(size_t)(by + i) * C + xx];
    __syncthreads();
    const int ox = by + threadIdx.x;
#pragma unroll
    for (int i = threadIdx.y; i < 32; i += 8)
        out[(size_t)(bx + i) * R + ox] = __float2half(tile[threadIdx.x][i]);
}

// =====================================================================
// fp16 mma flash attention — 64-key cp.async tiles, two 32-key steps,
// log2-domain softmax (Q pre-scaled by log2e/sqrt(d)), vote-gated
// rescale, diagonal-only masking, reversed q-tile order.
// =====================================================================
#define AROWB    272
#define AQ_SZ    (128 * AROWB)
#define AKV64_SZ (64 * AROWB)
#define ATSMEM   (AQ_SZ + 4 * AKV64_SZ)       // 104448

__global__ __launch_bounds__(256, 2)
void attn_mma(__half* __restrict__ Y)
{
    extern __shared__ char sm[];
    const uint32_t qs  = smem_u32(sm);
    const uint32_t ks0 = qs + AQ_SZ;
    const uint32_t vs0 = ks0 + 2 * AKV64_SZ;

    const int h    = blockIdx.y;
    const int kvh  = h >> 2;
    const int q0   = (int)(gridDim.x - 1 - blockIdx.x) * 128;
    const int tid  = threadIdx.x;
    const int warp = tid >> 5;
    const int lane = tid & 31;
    const int g    = lane >> 2;
    const int tg   = lane & 3;
    const int lr8  = lane & 7;
    const int rsel = (lane >> 3) & 1;
    const int ksel = (lane >> 4) & 1;

    const __half* Ksrc = g_kh + (size_t)kvh * T_SEQ * HEAD_D;
    const __half* Vsrc = g_vh + (size_t)kvh * T_SEQ * HEAD_D;

    {
        const __half* Qsrc = g_qh + (size_t)q0 * C_EMB + h * HEAD_D;
        for (int i = tid; i < 128 * 16; i += 256) {
            int row = i >> 4, c = i & 15;
            cp_async16(qs + (uint32_t)(row * AROWB + c * 16),
                       Qsrc + (size_t)row * C_EMB + c * 8);
        }
        cp_commit();
    }

    const int nt64 = q0 / 64 + 2;

    for (int i = tid; i < 64 * 16; i += 256) {
        int row = i >> 4, c = i & 15;
        cp_async16(ks0 + (uint32_t)(row * AROWB + c * 16),
                   Ksrc + (size_t)row * HEAD_D + c * 8);
        cp_async16(vs0 + (uint32_t)(row * AROWB + c * 16),
                   Vsrc + (size_t)row * HEAD_D + c * 8);
    }
    cp_commit();

    const uint32_t qa = qs + (uint32_t)((warp * 16 + lr8 + rsel * 8) * AROWB + ksel * 16);

    float O[16][4];
#pragma unroll
    for (int n = 0; n < 16; n++)
#pragma unroll
        for (int r = 0; r < 4; r++) O[n][r] = 0.f;
    float m0 = -1e30f, m1 = -1e30f, l0 = 0.f, l1 = 0.f;

    const int row0   = q0 + warp * 16 + g;
    const int wfirst = q0 + warp * 16;
    const int wlast  = wfirst + 15;

    for (int kt = 0; kt < nt64; kt++) {
        if (kt + 1 < nt64) {
            const uint32_t kb = ks0 + (uint32_t)(((kt + 1) & 1) * AKV64_SZ);
            const uint32_t vb = vs0 + (uint32_t)(((kt + 1) & 1) * AKV64_SZ);
            const __half* Ki = Ksrc + (size_t)(kt + 1) * 64 * HEAD_D;
            const __half* Vi = Vsrc + (size_t)(kt + 1) * 64 * HEAD_D;
            for (int i = tid; i < 64 * 16; i += 256) {
                int row = i >> 4, c = i & 15;
                cp_async16(kb + (uint32_t)(row * AROWB + c * 16),
                           Ki + (size_t)row * HEAD_D + c * 8);
                cp_async16(vb + (uint32_t)(row * AROWB + c * 16),
                           Vi + (size_t)row * HEAD_D + c * 8);
            }
            cp_commit();
            cp_wait<1>();
        } else {
            cp_wait<0>();
        }
        __syncthreads();

        const uint32_t kbuf = ks0 + (uint32_t)((kt & 1) * AKV64_SZ);
        const uint32_t vbuf = vs0 + (uint32_t)((kt & 1) * AKV64_SZ);

#pragma unroll
        for (int half = 0; half < 2; half++) {
            const int kk0 = kt * 64 + half * 32;
            if (kk0 > wlast) continue;

            const uint32_t ka = kbuf +
                (uint32_t)((half * 32 + lr8 + ksel * 8) * AROWB + rsel * 16);

            float S[4][4];
#pragma unroll
            for (int nt = 0; nt < 4; nt++)
#pragma unroll
                for (int r = 0; r < 4; r++) S[nt][r] = 0.f;

#pragma unroll
            for (int kc = 0; kc < 8; kc++) {
                unsigned aq[4], bk2[2][4];
                ldm_x4(aq, qa + (uint32_t)(kc * 32));
                ldm_x4(bk2[0], ka + (uint32_t)(kc * 32));
                ldm_x4(bk2[1], ka + (uint32_t)(16 * AROWB + kc * 32));
#pragma unroll
                for (int nt = 0; nt < 4; nt++)
                    mma_f16(S[nt], aq, &bk2[nt >> 1][(nt & 1) * 2]);
            }

            if (kk0 + 31 >= wfirst) {
#pragma unroll
                for (int nt = 0; nt < 4; nt++) {
                    int cb = kk0 + nt * 8 + 2 * tg;
                    S[nt][0] = (cb     <= row0)     ? S[nt][0] : -1e30f;
                    S[nt][1] = (cb + 1 <= row0)     ? S[nt][1] : -1e30f;
                    S[nt][2] = (cb     <= row0 + 8) ? S[nt][2] : -1e30f;
                    S[nt][3] = (cb + 1 <= row0 + 8) ? S[nt][3] : -1e30f;
                }
            }

            float rm0 = -1e30f, rm1 = -1e30f;
#pragma unroll
            for (int nt = 0; nt < 4; nt++) {
                rm0 = fmaxf(rm0, fmaxf(S[nt][0], S[nt][1]));
                rm1 = fmaxf(rm1, fmaxf(S[nt][2], S[nt][3]));
            }
            rm0 = fmaxf(rm0, __shfl_xor_sync(0xffffffffu, rm0, 1));
            rm0 = fmaxf(rm0, __shfl_xor_sync(0xffffffffu, rm0, 2));
            rm1 = fmaxf(rm1, __shfl_xor_sync(0xffffffffu, rm1, 1));
            rm1 = fmaxf(rm1, __shfl_xor_sync(0xffffffffu, rm1, 2));

            float mn0 = fmaxf(m0, rm0), mn1 = fmaxf(m1, rm1);

            unsigned upd = __ballot_sync(0xffffffffu, (mn0 > m0) || (mn1 > m1));
            if (upd) {
                float c0 = ex2(m0 - mn0), c1 = ex2(m1 - mn1);
                l0 *= c0; l1 *= c1;
#pragma unroll
                for (int n = 0; n < 16; n++) {
                    O[n][0] *= c0; O[n][1] *= c0;
                    O[n][2] *= c1; O[n][3] *= c1;
                }
                m0 = mn0; m1 = mn1;
            }

            float s0 = 0.f, s1 = 0.f;
#pragma unroll
            for (int nt = 0; nt < 4; nt++) {
                S[nt][0] = ex2(S[nt][0] - m0);
                S[nt][1] = ex2(S[nt][1] - m0);
                S[nt][2] = ex2(S[nt][2] - m1);
                S[nt][3] = ex2(S[nt][3] - m1);
                s0 += S[nt][0] + S[nt][1];
                s1 += S[nt][2] + S[nt][3];
            }
            s0 += __shfl_xor_sync(0xffffffffu, s0, 1);
            s0 += __shfl_xor_sync(0xffffffffu, s0, 2);
            s1 += __shfl_xor_sync(0xffffffffu, s1, 1);
            s1 += __shfl_xor_sync(0xffffffffu, s1, 2);
            l0 += s0;
            l1 += s1;

#pragma unroll
            for (int kc = 0; kc < 2; kc++) {
                unsigned pa[4];
                pa[0] = pack_h2(S[2 * kc][0],     S[2 * kc][1]);
                pa[1] = pack_h2(S[2 * kc][2],     S[2 * kc][3]);
                pa[2] = pack_h2(S[2 * kc + 1][0], S[2 * kc + 1][1]);
                pa[3] = pack_h2(S[2 * kc + 1][2], S[2 * kc + 1][3]);
                const uint32_t va = vbuf +
                    (uint32_t)((half * 32 + kc * 16 + lr8 + rsel * 8) * AROWB + ksel * 16);
#pragma unroll
                for (int dc = 0; dc < 8; dc++) {
                    unsigned vb[4];
                    ldm_x4t(vb, va + (uint32_t)(dc * 32));
                    mma_f16(O[dc * 2],     pa, &vb[0]);
                    mma_f16(O[dc * 2 + 1], pa, &vb[2]);
                }
            }
        }
        __syncthreads();
    }

    float inv0 = 1.f / l0, inv1 = 1.f / l1;
#pragma unroll
    for (int n = 0; n < 16; n++) {
        int c = h * HEAD_D + n * 8 + 2 * tg;
        __half2 h0 = __floats2half2_rn(O[n][0] * inv0, O[n][1] * inv0);
        __half2 h1 = __floats2half2_rn(O[n][2] * inv1, O[n][3] * inv1);
        *(__half2*)&Y[(size_t)row0 * C_EMB + c]       = h0;
        *(__half2*)&Y[(size_t)(row0 + 8) * C_EMB + c] = h1;
    }
}

// =====================================================================
// launch
// =====================================================================
extern "C" void kernel_launch(void* const* d_in, const int* in_sizes, int n_in,
                              void* d_out, int out_size)
{
    (void)in_sizes; (void)n_in; (void)out_size;
    const float* x    = (const float*)d_in[0];
    const float* cosb = (const float*)d_in[1];
    const float* sinb = (const float*)d_in[2];
    const float* Wq   = (const float*)d_in[3];
    const float* bq   = (const float*)d_in[4];
    const float* Wk   = (const float*)d_in[5];
    const float* bk   = (const float*)d_in[6];
    const float* Wv   = (const float*)d_in[7];
    const float* bv   = (const float*)d_in[8];
    const float* Wo   = (const float*)d_in[9];

    float* out   = (float*)d_out;
    float* out_y = out;
    float* out_k = out + (size_t)T_SEQ * C_EMB;
    float* out_v = out_k + (size_t)N_KVH * T_SEQ * HEAD_D;

    __half* yhb;  cudaGetSymbolAddress((void**)&yhb,  g_yh);
    __half* xhb;  cudaGetSymbolAddress((void**)&xhb,  g_xh);
    __half* wqkv; cudaGetSymbolAddress((void**)&wqkv, g_wqkvt);
    __half* wot;  cudaGetSymbolAddress((void**)&wot,  g_wot);
    float*  bqkv; cudaGetSymbolAddress((void**)&bqkv, g_bqkv);

    cudaFuncSetAttribute(gemm_h, cudaFuncAttributeMaxDynamicSharedMemorySize, GSMEM);
    cudaFuncSetAttribute(gemm_qkv, cudaFuncAttributeMaxDynamicSharedMemorySize, GSMEM);
    cudaFuncSetAttribute(attn_mma, cudaFuncAttributeMaxDynamicSharedMemorySize, ATSMEM);

    // 1: fused prep (weight transposes + bias concat + x->half)
    prep_kernel<<<dim3(64, 64, 5), dim3(32, 8)>>>(Wq, Wk, Wv, Wo, bq, bk, bv, x);

    // 2: QKV projection with fused RoPE epilogue
    gemm_qkv<<<dim3(QKV_W / 128, T_SEQ / 128), 128, GSMEM>>>(
        xhb, wqkv, bqkv, cosb, sinb, out_k, out_v, C_EMB);

    // 3: flash attention
    attn_mma<<<dim3(T_SEQ / 128, N_HEADS), 256, ATSMEM>>>(yhb);

    // 4: output projection  <-- ncu-captured launch
    gemm_h<<<dim3(C_EMB / 128, T_SEQ / 128), 128, GSMEM>>>(yhb, wot, nullptr, out_y, T_SEQ, C_EMB, C_EMB);
}